// round 13
// baseline (speedup 1.0000x reference)
#include <cuda_runtime.h>
#include <cuda_bf16.h>
#include <math.h>
#include <stdint.h>

// Problem dims (fixed)
#define BB 8
#define LL 1024
#define EE 1024
#define HH 16
#define DD 64
#define E3 3072
#define EPS 1e-5f

// ---------------- scratch (device globals; no allocation allowed) ----------
// "cell" = uint2 {hi_bf16x2, lo_bf16x2} for a pair of consecutive-K fp32 values.
__device__ __align__(128) uint2 g_qkvc[BB * LL * E3 / 2];               // 100 MB
__device__ float g_S[(size_t)BB * HH * LL * LL];                         // 512 MB
__device__ __align__(128) unsigned g_wb[(size_t)BB * HH * LL * LL / 2];  // W bf16 hi, 256 MB
__device__ __align__(128) uint2 g_vtc[BB * HH * DD * LL / 2];            // Vt cells, 32 MB
__device__ __align__(128) uint2 g_ctxc[BB * LL * EE / 2];                // ctx cells, 32 MB
__device__ __align__(128) uint2 g_xc[BB * LL * EE / 2];                  // x cells, 32 MB
__device__ __align__(128) uint2 g_wqc[E3 * EE / 2];                      // w_qkv cells, 12 MB
__device__ __align__(128) uint2 g_woc[EE * EE / 2];                      // w_out cells, 4 MB
__device__ float g_res[BB * LL * EE];                                    // 32 MB
__device__ float g_hn[BB * LL * EE];                                     // 32 MB
__device__ float g_avgpart[BB * HH * 8 * LL];
__device__ float g_poolpart[BB * 8 * EE];

// ---------------- helpers ----------------------------------------------------
__device__ __forceinline__ uint2 split2(float x0, float x1) {
    uint32_t hp, lp;
    asm("cvt.rn.bf16x2.f32 %0, %1, %2;" : "=r"(hp) : "f"(x1), "f"(x0));
    float h0 = __uint_as_float(hp << 16);
    float h1 = __uint_as_float(hp & 0xffff0000u);
    float l0 = x0 - h0;
    float l1 = x1 - h1;
    asm("cvt.rn.bf16x2.f32 %0, %1, %2;" : "=r"(lp) : "f"(l1), "f"(l0));
    return make_uint2(hp, lp);
}

__device__ __forceinline__ void mma16(float* d, const uint32_t* a, const uint32_t* b) {
    asm volatile(
        "mma.sync.aligned.m16n8k16.row.col.f32.bf16.bf16.f32 "
        "{%0,%1,%2,%3}, {%4,%5,%6,%7}, {%8,%9}, {%0,%1,%2,%3};"
        : "+f"(d[0]), "+f"(d[1]), "+f"(d[2]), "+f"(d[3])
        : "r"(a[0]), "r"(a[1]), "r"(a[2]), "r"(a[3]), "r"(b[0]), "r"(b[1]));
}

__device__ __forceinline__ void cp16(uint32_t dst, const void* src) {
    asm volatile("cp.async.cg.shared.global [%0], [%1], 16;"
                 :: "r"(dst), "l"(__cvta_generic_to_global(src)) : "memory");
}
__device__ __forceinline__ void cp_commit() {
    asm volatile("cp.async.commit_group;" ::: "memory");
}
template <int N>
__device__ __forceinline__ void cp_wait() {
    asm volatile("cp.async.wait_group %0;" :: "n"(N) : "memory");
}

// ---------------- pre-split kernel: fp32 -> cells ----------------------------
__global__ __launch_bounds__(256) void split_kernel(const float2* __restrict__ src,
                                                    uint2* __restrict__ dst, int n) {
    int i = blockIdx.x * 256 + threadIdx.x;
    int stride = gridDim.x * 256;
    for (; i < n; i += stride) {
        float2 v = src[i];
        dst[i] = split2(v.x, v.y);
    }
}

// ---------------- cp.async bf16-cell tensor-core GEMM ------------------------
// C[128*gy, TN*gx] = alpha * A(M,K) * B(N,K)^T (+bias) (+resid)
// A: ASPLIT ? uint2 cells (3-term) : uint hi-cells (2-term). B: uint2 cells.
// ld*C in cells (= K_fp32/2). OUTC: write C as split cells (else fp32).
// Batched via blockIdx.z = bo*inner + bi (A/B strides in cells, C in fp32).
// K32 per pipeline stage, 2-stage double buffer, 2 CTAs/SM.
template <int TN, bool ASPLIT, bool OUTC>
__global__ __launch_bounds__(256, 2) void cgemm(
    const void* __restrict__ Ap_, const uint2* __restrict__ Bp,
    float* __restrict__ C,
    const float* __restrict__ bias, const float* __restrict__ resid,
    int K, int ldaC, int ldbC, int ldc,
    long long sAo, long long sAi, long long sBo, long long sBi,
    long long sCo, long long sCi, int inner, float alpha)
{
    extern __shared__ __align__(16) char sm[];
    constexpr int KPS2 = 20;                       // 16 cells + 4 pad per row
    constexpr int ABYTES = ASPLIT ? 128 * KPS2 * 8 : 128 * KPS2 * 4;
    constexpr int BBYTES = TN * KPS2 * 8;
    constexpr int SLOT = ABYTES + BBYTES;

    const int tid = threadIdx.x;
    const int warp = tid >> 5, lane = tid & 31;
    const int g = lane >> 2, tg = lane & 3;

    int bz = blockIdx.z;
    int bo = bz / inner, bi = bz % inner;
    long long aoff = bo * sAo + bi * sAi;
    Bp += bo * sBo + bi * sBi;
    long long coff = bo * sCo + bi * sCi;
    C += coff;
    const float* Rp = resid ? resid + coff : nullptr;

    const int bm = blockIdx.y * 128;
    const int bn = blockIdx.x * TN;

    constexpr int WN = TN / 4;        // 32 or 16
    constexpr int MT = 4;
    constexpr int NTL = WN / 8;       // 4 or 2
    const int wm = (warp >> 2) * 64;
    const int wn = (warp & 3) * WN;

    float acc[MT][NTL][4];
#pragma unroll
    for (int i = 0; i < MT; i++)
#pragma unroll
        for (int j = 0; j < NTL; j++)
#pragma unroll
            for (int q = 0; q < 4; q++) acc[i][j][q] = 0.f;

    uint32_t sb;
    asm("{ .reg .u64 t; cvta.to.shared.u64 t, %1; cvt.u32.u64 %0, t; }"
        : "=r"(sb) : "l"(sm));

    // ---- staging pointers: one A row and one B row per thread
    // ASPLIT A: 128 rows x 16 cells (128B) = 8x16B chunks; 2 thr/row, 4 chunks each
    // hi A:     128 rows x 16 cells (64B)  = 4x16B chunks; 2 thr/row, 2 chunks each
    // B TN=128: as split A.  B TN=64: 4 thr/row, 2 chunks each.
    const uint2* aP = nullptr;
    const unsigned* aH = nullptr;
    uint32_t aD;
    {
        int row = tid >> 1;
        if (ASPLIT) {
            int aj = (tid & 1) * 4;
            aP = (const uint2*)Ap_ + aoff + (long long)(bm + row) * ldaC + aj * 2;
            aD = (uint32_t)(row * (KPS2 * 8) + aj * 16);
        } else {
            int aj = (tid & 1) * 2;
            aH = (const unsigned*)Ap_ + aoff + (long long)(bm + row) * ldaC + aj * 4;
            aD = (uint32_t)(row * (KPS2 * 4) + aj * 16);
        }
    }
    const int brow = (TN == 128) ? (tid >> 1) : (tid >> 2);
    const int bj   = (TN == 128) ? ((tid & 1) * 4) : ((tid & 3) * 2);
    const uint2* bP = Bp + (long long)(bn + brow) * ldbC + bj * 2;
    const uint32_t bD = (uint32_t)(ABYTES + brow * (KPS2 * 8) + bj * 16);
    constexpr int NBQ = (TN == 128) ? 4 : 2;

    const int nc = K / 32;

    auto stage = [&](int c, int slot) {
        uint32_t base = sb + slot * SLOT;
        if (ASPLIT) {
#pragma unroll
            for (int q = 0; q < 4; q++)
                cp16(base + aD + q * 16, aP + c * 16 + q * 2);
        } else {
#pragma unroll
            for (int q = 0; q < 2; q++)
                cp16(base + aD + q * 16, aH + c * 16 + q * 4);
        }
#pragma unroll
        for (int q = 0; q < NBQ; q++)
            cp16(base + bD + q * 16, bP + c * 16 + q * 2);
    };

    stage(0, 0);
    cp_commit();

    int buf = 0;
    for (int c = 0; c < nc; c++) {
        if (c + 1 < nc) { stage(c + 1, buf ^ 1); cp_commit(); cp_wait<1>(); }
        else            { cp_wait<0>(); }
        __syncthreads();

        const char* slotbase = sm + buf * SLOT;
        const uint2* bs = (const uint2*)(slotbase + ABYTES);
#pragma unroll
        for (int ks = 0; ks < 2; ks++) {
            const int kb = 8 * ks;
            uint2 bfr[NTL][2];
#pragma unroll
            for (int nt = 0; nt < NTL; nt++) {
                int c0 = wn + nt * 8 + g;
                bfr[nt][0] = bs[c0 * KPS2 + kb + tg];
                bfr[nt][1] = bs[c0 * KPS2 + kb + tg + 4];
            }
            if (ASPLIT) {
                const uint2* as = (const uint2*)slotbase;
#pragma unroll
                for (int mt = 0; mt < MT; mt++) {
                    int rr = wm + mt * 16 + g;
                    uint2 f0 = as[rr * KPS2 + kb + tg];
                    uint2 f1 = as[(rr + 8) * KPS2 + kb + tg];
                    uint2 f2 = as[rr * KPS2 + kb + tg + 4];
                    uint2 f3 = as[(rr + 8) * KPS2 + kb + tg + 4];
                    uint32_t ah[4] = {f0.x, f1.x, f2.x, f3.x};
                    uint32_t al[4] = {f0.y, f1.y, f2.y, f3.y};
#pragma unroll
                    for (int nt = 0; nt < NTL; nt++) {
                        uint32_t bh[2] = {bfr[nt][0].x, bfr[nt][1].x};
                        uint32_t bl[2] = {bfr[nt][0].y, bfr[nt][1].y};
                        mma16(acc[mt][nt], ah, bh);
                        mma16(acc[mt][nt], ah, bl);
                        mma16(acc[mt][nt], al, bh);
                    }
                }
            } else {
                const unsigned* as = (const unsigned*)slotbase;
#pragma unroll
                for (int mt = 0; mt < MT; mt++) {
                    int rr = wm + mt * 16 + g;
                    uint32_t ah[4];
                    ah[0] = as[rr * KPS2 + kb + tg];
                    ah[1] = as[(rr + 8) * KPS2 + kb + tg];
                    ah[2] = as[rr * KPS2 + kb + tg + 4];
                    ah[3] = as[(rr + 8) * KPS2 + kb + tg + 4];
#pragma unroll
                    for (int nt = 0; nt < NTL; nt++) {
                        uint32_t bh[2] = {bfr[nt][0].x, bfr[nt][1].x};
                        uint32_t bl[2] = {bfr[nt][0].y, bfr[nt][1].y};
                        mma16(acc[mt][nt], ah, bh);
                        mma16(acc[mt][nt], ah, bl);
                    }
                }
            }
        }
        buf ^= 1;
        __syncthreads();   // WAR: next iteration stages into the buffer just read
    }

    // ---- epilogue
#pragma unroll
    for (int mt = 0; mt < MT; mt++) {
#pragma unroll
        for (int nt = 0; nt < NTL; nt++) {
            int c = bn + wn + nt * 8 + 2 * tg;
#pragma unroll
            for (int hrow = 0; hrow < 2; hrow++) {
                int gr = bm + wm + mt * 16 + g + hrow * 8;
                float vx = acc[mt][nt][2 * hrow] * alpha;
                float vy = acc[mt][nt][2 * hrow + 1] * alpha;
                if (bias) { vx += bias[c]; vy += bias[c + 1]; }
                long long ci = (long long)gr * ldc + c;
                if (Rp) {
                    float2 rr = *reinterpret_cast<const float2*>(&Rp[ci]);
                    vx += rr.x; vy += rr.y;
                }
                if (OUTC) {
                    reinterpret_cast<uint2*>(C)[ci >> 1] = split2(vx, vy);
                } else {
                    float2 o; o.x = vx; o.y = vy;
                    *reinterpret_cast<float2*>(&C[ci]) = o;
                }
            }
        }
    }
}

// ---------------- V transpose (cells -> transposed cells) --------------------
__global__ __launch_bounds__(256) void vtrans_kernel(const uint2* __restrict__ qc,
                                                     uint2* __restrict__ vt) {
    __shared__ ushort hiS[32][33];
    __shared__ ushort loS[32][33];
    int bh = blockIdx.z;
    int b = bh >> 4, h = bh & 15;
    int lb = blockIdx.x * 32, db = blockIdx.y * 32;
    int t = threadIdx.x;
    int l = t >> 3, cj = t & 7;
#pragma unroll
    for (int p = 0; p < 2; p++) {
        int j = cj + 8 * p;  // local d-cell 0..15
        long long idx = (long long)(b * LL + lb + l) * (E3 / 2) + 1024 + h * 32 + (db >> 1) + j;
        uint2 cell = qc[idx];
        hiS[l][2 * j]     = (ushort)(cell.x & 0xffffu);
        hiS[l][2 * j + 1] = (ushort)(cell.x >> 16);
        loS[l][2 * j]     = (ushort)(cell.y & 0xffffu);
        loS[l][2 * j + 1] = (ushort)(cell.y >> 16);
    }
    __syncthreads();
    int d = t >> 3;
#pragma unroll
    for (int p = 0; p < 2; p++) {
        int jj = cj + 8 * p;  // local l-pair 0..15
        uint2 cell;
        cell.x = (uint32_t)hiS[2 * jj][d] | ((uint32_t)hiS[2 * jj + 1][d] << 16);
        cell.y = (uint32_t)loS[2 * jj][d] | ((uint32_t)loS[2 * jj + 1][d] << 16);
        long long dst = (long long)bh * (DD * LL / 2) + (long long)(db + d) * (LL / 2) + (lb >> 1) + jj;
        vt[dst] = cell;
    }
}

// ---------------- block reductions -----------------------------------------
__device__ __forceinline__ float blk_reduce_sum(float v, float* sm) {
#pragma unroll
    for (int o = 16; o > 0; o >>= 1) v += __shfl_xor_sync(0xffffffffu, v, o);
    int w = threadIdx.x >> 5;
    if ((threadIdx.x & 31) == 0) sm[w] = v;
    __syncthreads();
    if (threadIdx.x == 0) {
        float s = 0.f;
        int nw = blockDim.x >> 5;
        for (int i = 0; i < nw; i++) s += sm[i];
        sm[0] = s;
    }
    __syncthreads();
    float r = sm[0];
    __syncthreads();
    return r;
}

__device__ __forceinline__ float blk_reduce_max(float v, float* sm) {
#pragma unroll
    for (int o = 16; o > 0; o >>= 1)
        v = fmaxf(v, __shfl_xor_sync(0xffffffffu, v, o));
    int w = threadIdx.x >> 5;
    if ((threadIdx.x & 31) == 0) sm[w] = v;
    __syncthreads();
    if (threadIdx.x == 0) {
        float s = sm[0];
        int nw = blockDim.x >> 5;
        for (int i = 1; i < nw; i++) s = fmaxf(s, sm[i]);
        sm[0] = s;
    }
    __syncthreads();
    float r = sm[0];
    __syncthreads();
    return r;
}

// ---------------- softmax: read S fp32, write W bf16 (hi only) ---------------
__global__ __launch_bounds__(256) void softmax_kernel(const float* __restrict__ S,
                                                      unsigned* __restrict__ Wb) {
    __shared__ float sm[32];
    long long row = blockIdx.x;
    const float* p = S + row * (long long)LL;
    float4 v = reinterpret_cast<const float4*>(p)[threadIdx.x];
    float mx = fmaxf(fmaxf(v.x, v.y), fmaxf(v.z, v.w));
    mx = blk_reduce_max(mx, sm);
    v.x = __expf(v.x - mx);
    v.y = __expf(v.y - mx);
    v.z = __expf(v.z - mx);
    v.w = __expf(v.w - mx);
    float s = v.x + v.y + v.z + v.w;
    s = blk_reduce_sum(s, sm);
    float inv = 1.f / s;
    v.x *= inv; v.y *= inv; v.z *= inv; v.w *= inv;
    uint32_t p0, p1;
    asm("cvt.rn.bf16x2.f32 %0, %1, %2;" : "=r"(p0) : "f"(v.y), "f"(v.x));
    asm("cvt.rn.bf16x2.f32 %0, %1, %2;" : "=r"(p1) : "f"(v.w), "f"(v.z));
    reinterpret_cast<uint2*>(Wb + row * 512)[threadIdx.x] = make_uint2(p0, p1);
}

// ---------------- avg_attn from bf16 W ---------------------------------------
__global__ __launch_bounds__(256) void avg_part_kernel(const unsigned* __restrict__ Wb,
                                                       float* __restrict__ ap) {
    int m2 = blockIdx.x * 256 + threadIdx.x;   // column-pair index
    int lc = blockIdx.y;
    int bh = blockIdx.z;
    const unsigned* p = Wb + (long long)bh * LL * (LL / 2) +
                        (long long)lc * 128 * (LL / 2) + m2;
    float s0 = 0.f, s1 = 0.f;
#pragma unroll 8
    for (int l = 0; l < 128; l++) {
        unsigned u = p[(long long)l * (LL / 2)];
        s0 += __uint_as_float(u << 16);
        s1 += __uint_as_float(u & 0xffff0000u);
    }
    float* dst = ap + ((bh * 8 + lc) * LL) + 2 * m2;
    dst[0] = s0;
    dst[1] = s1;
}

__global__ __launch_bounds__(256) void avg_final_kernel(const float* __restrict__ ap,
                                                        float* __restrict__ out) {
    int m = blockIdx.x * 256 + threadIdx.x;
    int b = blockIdx.y;
    float s = 0.f;
#pragma unroll
    for (int h = 0; h < HH; h++)
#pragma unroll
        for (int lc = 0; lc < 8; lc++)
            s += ap[((b * HH + h) * 8 + lc) * LL + m];
    out[BB * EE + b * LL + m] = s * (1.f / (HH * (float)LL));
}

// ---------------- LayerNorm ---------------------------------------------------
__global__ __launch_bounds__(256) void ln_kernel(const float* __restrict__ h,
                                                 const float* __restrict__ gamma,
                                                 const float* __restrict__ beta,
                                                 float* __restrict__ hn) {
    __shared__ float sm[32];
    long long row = blockIdx.x;
    const float* p = h + row * (long long)EE;
    float4 v = reinterpret_cast<const float4*>(p)[threadIdx.x];
    float s = v.x + v.y + v.z + v.w;
    s = blk_reduce_sum(s, sm);
    float mean = s * (1.f / EE);
    float dx = v.x - mean, dy = v.y - mean, dz = v.z - mean, dw = v.w - mean;
    float sq = dx * dx + dy * dy + dz * dz + dw * dw;
    sq = blk_reduce_sum(sq, sm);
    float r = rsqrtf(sq * (1.f / EE) + EPS);
    float4 gm = reinterpret_cast<const float4*>(gamma)[threadIdx.x];
    float4 bt = reinterpret_cast<const float4*>(beta)[threadIdx.x];
    float4 o;
    o.x = dx * r * gm.x + bt.x;
    o.y = dy * r * gm.y + bt.y;
    o.z = dz * r * gm.z + bt.z;
    o.w = dw * r * gm.w + bt.w;
    reinterpret_cast<float4*>(hn + row * (long long)EE)[threadIdx.x] = o;
}

// ---------------- pooled mean -------------------------------------------------
__global__ __launch_bounds__(256) void pooled_part_kernel(const float* __restrict__ hn,
                                                          float* __restrict__ pp) {
    int e = blockIdx.x * 256 + threadIdx.x;
    int lc = blockIdx.y;
    int b = blockIdx.z;
    const float* p = hn + ((long long)b * LL + lc * 128) * EE + e;
    float s = 0.f;
#pragma unroll 8
    for (int l = 0; l < 128; l++) s += p[(long long)l * EE];
    pp[(b * 8 + lc) * EE + e] = s;
}

__global__ __launch_bounds__(256) void pooled_final_kernel(const float* __restrict__ pp,
                                                           float* __restrict__ out) {
    int e = blockIdx.x * 256 + threadIdx.x;
    int b = blockIdx.y;
    float s = 0.f;
#pragma unroll
    for (int lc = 0; lc < 8; lc++) s += pp[(b * 8 + lc) * EE + e];
    out[b * EE + e] = s * (1.f / (float)LL);
}

// ---------------- launch -----------------------------------------------------
extern "C" void kernel_launch(void* const* d_in, const int* in_sizes, int n_in,
                              void* d_out, int out_size) {
    const float* x     = (const float*)d_in[0];
    const float* w_qkv = (const float*)d_in[1];
    const float* b_qkv = (const float*)d_in[2];
    const float* w_out = (const float*)d_in[3];
    const float* b_out = (const float*)d_in[4];
    const float* gamma = (const float*)d_in[5];
    const float* beta  = (const float*)d_in[6];
    float* out = (float*)d_out;

    uint2 *qkvc, *vtc, *ctxc, *xc, *wqc, *woc;
    unsigned* wb;
    float *S, *res, *hn, *ap, *pp;
    cudaGetSymbolAddress((void**)&qkvc, g_qkvc);
    cudaGetSymbolAddress((void**)&S,    g_S);
    cudaGetSymbolAddress((void**)&wb,   g_wb);
    cudaGetSymbolAddress((void**)&vtc,  g_vtc);
    cudaGetSymbolAddress((void**)&ctxc, g_ctxc);
    cudaGetSymbolAddress((void**)&xc,   g_xc);
    cudaGetSymbolAddress((void**)&wqc,  g_wqc);
    cudaGetSymbolAddress((void**)&woc,  g_woc);
    cudaGetSymbolAddress((void**)&res,  g_res);
    cudaGetSymbolAddress((void**)&hn,   g_hn);
    cudaGetSymbolAddress((void**)&ap,   g_avgpart);
    cudaGetSymbolAddress((void**)&pp,   g_poolpart);

    const int M = BB * LL;  // 8192
    constexpr int KPS2 = 20;
    const int SM_SPLIT128 = 2 * (128 * KPS2 * 8 + 128 * KPS2 * 8);  // 81920
    const int SM_HI64     = 2 * (128 * KPS2 * 4 + 64 * KPS2 * 8);   // 40960
    cudaFuncSetAttribute((const void*)cgemm<128, true, true>,
                         cudaFuncAttributeMaxDynamicSharedMemorySize, SM_SPLIT128);
    cudaFuncSetAttribute((const void*)cgemm<128, true, false>,
                         cudaFuncAttributeMaxDynamicSharedMemorySize, SM_SPLIT128);
    cudaFuncSetAttribute((const void*)cgemm<64, false, true>,
                         cudaFuncAttributeMaxDynamicSharedMemorySize, SM_HI64);

    // 0) pre-split inputs to bf16 cells
    split_kernel<<<512, 256>>>((const float2*)x, xc, BB * LL * EE / 2);
    split_kernel<<<512, 256>>>((const float2*)w_qkv, wqc, E3 * EE / 2);
    split_kernel<<<256, 256>>>((const float2*)w_out, woc, EE * EE / 2);

    // 1) QKV projection -> qkv cells (8192 x 3072 x 1024)
    {
        dim3 grid(E3 / 128, M / 128, 1);
        cgemm<128, true, true><<<grid, 256, SM_SPLIT128>>>(
            xc, wqc, (float*)qkvc, b_qkv, nullptr,
            EE, EE / 2, EE / 2, E3,
            0, 0, 0, 0, 0, 0, 1, 1.0f);
    }

    // 1b) Vt cells
    {
        dim3 grid(LL / 32, DD / 32, BB * HH);
        vtrans_kernel<<<grid, 256>>>(qkvc, vtc);
    }

    // 2) scores -> S fp32 (1024x1024x64, 128 batches)
    {
        dim3 grid(LL / 128, LL / 128, BB * HH);
        cgemm<128, true, false><<<grid, 256, SM_SPLIT128>>>(
            qkvc /*Q*/, qkvc + EE / 2 /*K*/, S, nullptr, nullptr,
            DD, E3 / 2, E3 / 2, LL,
            (long long)LL * E3 / 2, DD / 2,
            (long long)LL * E3 / 2, DD / 2,
            (long long)HH * LL * LL, (long long)LL * LL,
            HH, 0.125f);
    }

    // 3) softmax -> W bf16
    softmax_kernel<<<BB * HH * LL, 256>>>(S, wb);

    // 4) avg_attn
    {
        dim3 g1(LL / 512, 8, BB * HH);
        avg_part_kernel<<<g1, 256>>>(wb, ap);
        dim3 g2(LL / 256, BB);
        avg_final_kernel<<<g2, 256>>>(ap, out);
    }

    // 5) ctx = W(bf16 hi) @ Vt^T -> ctx cells (1024 x 64 x 1024, 128 batches)
    {
        dim3 grid(1, LL / 128, BB * HH);
        cgemm<64, false, true><<<grid, 256, SM_HI64>>>(
            wb, vtc, (float*)ctxc, nullptr, nullptr,
            LL, LL / 2, LL / 2, EE,
            (long long)HH * LL * LL / 2, (long long)LL * LL / 2,
            (long long)HH * DD * LL / 2, (long long)DD * LL / 2,
            (long long)LL * EE, (long long)DD,
            HH, 1.0f);
    }

    // 6) out proj + bias + residual -> res fp32
    {
        dim3 grid(EE / 128, M / 128, 1);
        cgemm<128, true, false><<<grid, 256, SM_SPLIT128>>>(
            ctxc, woc, res, b_out, x,
            EE, EE / 2, EE / 2, EE,
            0, 0, 0, 0, 0, 0, 1, 1.0f);
    }

    // 7) layernorm
    ln_kernel<<<M, 256>>>(res, gamma, beta, hn);

    // 8) pooled mean
    {
        dim3 g1(EE / 256, 8, BB);
        pooled_part_kernel<<<g1, 256>>>(hn, pp);
        dim3 g2(EE / 256, BB);
        pooled_final_kernel<<<g2, 256>>>(pp, out);
    }
}

// round 14
// speedup vs baseline: 1.1458x; 1.1458x over previous
#include <cuda_runtime.h>
#include <cuda_bf16.h>
#include <math.h>
#include <stdint.h>

// Problem dims (fixed)
#define BB 8
#define LL 1024
#define EE 1024
#define HH 16
#define DD 64
#define E3 3072
#define EPS 1e-5f

// ---------------- scratch (device globals; no allocation allowed) ----------
// "cell" = uint2 {hi_bf16x2, lo_bf16x2} for a pair of consecutive-K fp32 values.
__device__ __align__(128) uint2 g_qkvc[BB * LL * E3 / 2];               // 100 MB
__device__ float g_S[(size_t)BB * HH * LL * LL];                         // 512 MB
__device__ __align__(128) unsigned g_wb[(size_t)BB * HH * LL * LL / 2];  // W bf16 hi, 256 MB
__device__ __align__(128) uint2 g_vtc[BB * HH * DD * LL / 2];            // Vt cells, 32 MB
__device__ __align__(128) uint2 g_ctxc[BB * LL * EE / 2];                // ctx cells, 32 MB
__device__ __align__(128) uint2 g_xc[BB * LL * EE / 2];                  // x cells, 32 MB
__device__ __align__(128) uint2 g_wqc[E3 * EE / 2];                      // w_qkv cells, 12 MB
__device__ __align__(128) uint2 g_woc[EE * EE / 2];                      // w_out cells, 4 MB
__device__ float g_res[BB * LL * EE];                                    // 32 MB
__device__ float g_hn[BB * LL * EE];                                     // 32 MB
__device__ float g_avgpart[BB * HH * 8 * LL];
__device__ float g_poolpart[BB * 8 * EE];

// ---------------- helpers ----------------------------------------------------
__device__ __forceinline__ uint2 split2(float x0, float x1) {
    uint32_t hp, lp;
    asm("cvt.rn.bf16x2.f32 %0, %1, %2;" : "=r"(hp) : "f"(x1), "f"(x0));
    float h0 = __uint_as_float(hp << 16);
    float h1 = __uint_as_float(hp & 0xffff0000u);
    float l0 = x0 - h0;
    float l1 = x1 - h1;
    asm("cvt.rn.bf16x2.f32 %0, %1, %2;" : "=r"(lp) : "f"(l1), "f"(l0));
    return make_uint2(hp, lp);
}

__device__ __forceinline__ void mma16(float* d, const uint32_t* a, const uint32_t* b) {
    asm volatile(
        "mma.sync.aligned.m16n8k16.row.col.f32.bf16.bf16.f32 "
        "{%0,%1,%2,%3}, {%4,%5,%6,%7}, {%8,%9}, {%0,%1,%2,%3};"
        : "+f"(d[0]), "+f"(d[1]), "+f"(d[2]), "+f"(d[3])
        : "r"(a[0]), "r"(a[1]), "r"(a[2]), "r"(a[3]), "r"(b[0]), "r"(b[1]));
}

__device__ __forceinline__ void cp16(uint32_t dst, const void* src) {
    asm volatile("cp.async.cg.shared.global [%0], [%1], 16;"
                 :: "r"(dst), "l"(__cvta_generic_to_global(src)) : "memory");
}
__device__ __forceinline__ void cp_commit() {
    asm volatile("cp.async.commit_group;" ::: "memory");
}
template <int N>
__device__ __forceinline__ void cp_wait() {
    asm volatile("cp.async.wait_group %0;" :: "n"(N) : "memory");
}

// ---------------- pre-split kernel: fp32 -> cells ----------------------------
__global__ __launch_bounds__(256) void split_kernel(const float2* __restrict__ src,
                                                    uint2* __restrict__ dst, int n) {
    int i = blockIdx.x * 256 + threadIdx.x;
    int stride = gridDim.x * 256;
    for (; i < n; i += stride) {
        float2 v = src[i];
        dst[i] = split2(v.x, v.y);
    }
}

// ---------------- cp.async bf16-cell tensor-core GEMM ------------------------
// C[128*gy, TN*gx] = alpha * A(M,K) * B(N,K)^T (+bias) (+resid)
// A: ASPLIT ? uint2 cells (3-term) : uint hi-cells (2-term). B: uint2 cells.
// ld*C in cells (= K_fp32/2). OUTC: write C as split cells (else fp32).
// Batched via blockIdx.z = bo*inner + bi (A/B strides in cells, C in fp32).
// 3-stage cp.async ring, ONE __syncthreads per K16 chunk, 2 CTAs/SM.
// Hazard analysis for single barrier: at iter c every thread passed the top
// barrier only after finishing compute(c-1), the last reader of slot (c+2)%3,
// so stage(c+2) issued post-barrier cannot clobber in-flight reads.
template <int TN, bool ASPLIT, bool OUTC>
__global__ __launch_bounds__(256, 2) void cgemm(
    const void* __restrict__ Ap_, const uint2* __restrict__ Bp,
    float* __restrict__ C,
    const float* __restrict__ bias, const float* __restrict__ resid,
    int K, int ldaC, int ldbC, int ldc,
    long long sAo, long long sAi, long long sBo, long long sBi,
    long long sCo, long long sCi, int inner, float alpha)
{
    extern __shared__ __align__(16) char sm[];
    constexpr int KPS = 12;                        // 8 cells + 4 pad
    constexpr int ABYTES = ASPLIT ? 128 * KPS * 8 : 128 * KPS * 4;
    constexpr int BBYTES = TN * KPS * 8;
    constexpr int SLOT = ABYTES + BBYTES;

    const int tid = threadIdx.x;
    const int warp = tid >> 5, lane = tid & 31;
    const int g = lane >> 2, tg = lane & 3;

    int bz = blockIdx.z;
    int bo = bz / inner, bi = bz % inner;
    long long aoff = bo * sAo + bi * sAi;
    Bp += bo * sBo + bi * sBi;
    long long coff = bo * sCo + bi * sCi;
    C += coff;
    const float* Rp = resid ? resid + coff : nullptr;

    const int bm = blockIdx.y * 128;
    const int bn = blockIdx.x * TN;

    constexpr int WN = TN / 4;        // 32 or 16
    constexpr int MT = 4;
    constexpr int NTL = WN / 8;       // 4 or 2
    const int wm = (warp >> 2) * 64;
    const int wn = (warp & 3) * WN;

    float acc[MT][NTL][4];
#pragma unroll
    for (int i = 0; i < MT; i++)
#pragma unroll
        for (int j = 0; j < NTL; j++)
#pragma unroll
            for (int q = 0; q < 4; q++) acc[i][j][q] = 0.f;

    uint32_t sb;
    asm("{ .reg .u64 t; cvta.to.shared.u64 t, %1; cvt.u32.u64 %0, t; }"
        : "=r"(sb) : "l"(sm));

    // ---- precomputed staging pointers (advance by 8 elems per chunk)
    const int r0 = tid >> 2, j4 = tid & 3;        // 64-row groups, 16B chunk
    const int r1 = tid >> 1, j2 = tid & 1;        // 128 rows, 16B chunk (hi-only A)
    const uint2* aS0;
    const uint2* aS1;
    const unsigned* aH;
    if (ASPLIT) {
        const uint2* A2 = (const uint2*)Ap_ + aoff;
        aS0 = A2 + (long long)(bm + r0) * ldaC + 2 * j4;
        aS1 = A2 + (long long)(bm + r0 + 64) * ldaC + 2 * j4;
        aH = nullptr;
    } else {
        const unsigned* A1 = (const unsigned*)Ap_ + aoff;
        aH = A1 + (long long)(bm + r1) * ldaC + 4 * j2;
        aS0 = aS1 = nullptr;
    }
    const uint2* bS0 = Bp + (long long)(bn + r0) * ldbC + 2 * j4;
    const uint2* bS1 = (TN == 128) ? Bp + (long long)(bn + r0 + 64) * ldbC + 2 * j4
                                   : nullptr;
    const uint32_t aD0 = ASPLIT ? (uint32_t)(r0 * (KPS * 8) + 16 * j4)
                                : (uint32_t)(r1 * (KPS * 4) + 16 * j2);
    const uint32_t aD1 = ASPLIT ? (uint32_t)((r0 + 64) * (KPS * 8) + 16 * j4) : 0;
    const uint32_t bD0 = (uint32_t)(ABYTES + r0 * (KPS * 8) + 16 * j4);
    const uint32_t bD1 = (uint32_t)(ABYTES + (r0 + 64) * (KPS * 8) + 16 * j4);

    const int nc = K / 16;

    auto stage = [&](int c, int slot) {
        uint32_t base = sb + slot * SLOT;
        if (ASPLIT) {
            cp16(base + aD0, aS0 + c * 8);
            cp16(base + aD1, aS1 + c * 8);
        } else {
            cp16(base + aD0, aH + c * 8);
        }
        cp16(base + bD0, bS0 + c * 8);
        if (TN == 128) cp16(base + bD1, bS1 + c * 8);
    };

    stage(0, 0); cp_commit();
    stage(1, 1); cp_commit();

    int slot = 0;
    for (int c = 0; c < nc; c++) {
        if (c + 1 < nc) cp_wait<1>();
        else            cp_wait<0>();
        __syncthreads();
        {
            int ns = slot + 2; if (ns >= 3) ns -= 3;
            if (c + 2 < nc) { stage(c + 2, ns); cp_commit(); }
        }

        const char* slotbase = sm + slot * SLOT;
        const uint2* bs = (const uint2*)(slotbase + ABYTES);
        uint2 bfr[NTL][2];
#pragma unroll
        for (int nt = 0; nt < NTL; nt++) {
            int c0 = wn + nt * 8 + g;
            bfr[nt][0] = bs[c0 * KPS + tg];
            bfr[nt][1] = bs[c0 * KPS + tg + 4];
        }

        if (ASPLIT) {
            const uint2* as = (const uint2*)slotbase;
#pragma unroll
            for (int mt = 0; mt < MT; mt++) {
                int rr = wm + mt * 16 + g;
                uint2 f0 = as[rr * KPS + tg];
                uint2 f1 = as[(rr + 8) * KPS + tg];
                uint2 f2 = as[rr * KPS + tg + 4];
                uint2 f3 = as[(rr + 8) * KPS + tg + 4];
                uint32_t ah[4] = {f0.x, f1.x, f2.x, f3.x};
                uint32_t al[4] = {f0.y, f1.y, f2.y, f3.y};
#pragma unroll
                for (int nt = 0; nt < NTL; nt++) {
                    uint32_t bh[2] = {bfr[nt][0].x, bfr[nt][1].x};
                    uint32_t bl[2] = {bfr[nt][0].y, bfr[nt][1].y};
                    mma16(acc[mt][nt], ah, bh);
                    mma16(acc[mt][nt], ah, bl);
                    mma16(acc[mt][nt], al, bh);
                }
            }
        } else {
            const unsigned* as = (const unsigned*)slotbase;
#pragma unroll
            for (int mt = 0; mt < MT; mt++) {
                int rr = wm + mt * 16 + g;
                uint32_t ah[4];
                ah[0] = as[rr * KPS + tg];
                ah[1] = as[(rr + 8) * KPS + tg];
                ah[2] = as[rr * KPS + tg + 4];
                ah[3] = as[(rr + 8) * KPS + tg + 4];
#pragma unroll
                for (int nt = 0; nt < NTL; nt++) {
                    uint32_t bh[2] = {bfr[nt][0].x, bfr[nt][1].x};
                    uint32_t bl[2] = {bfr[nt][0].y, bfr[nt][1].y};
                    mma16(acc[mt][nt], ah, bh);
                    mma16(acc[mt][nt], ah, bl);
                }
            }
        }
        slot = (slot == 2) ? 0 : slot + 1;
    }

    // ---- epilogue
#pragma unroll
    for (int mt = 0; mt < MT; mt++) {
#pragma unroll
        for (int nt = 0; nt < NTL; nt++) {
            int c = bn + wn + nt * 8 + 2 * tg;
#pragma unroll
            for (int hrow = 0; hrow < 2; hrow++) {
                int gr = bm + wm + mt * 16 + g + hrow * 8;
                float vx = acc[mt][nt][2 * hrow] * alpha;
                float vy = acc[mt][nt][2 * hrow + 1] * alpha;
                if (bias) { vx += bias[c]; vy += bias[c + 1]; }
                long long ci = (long long)gr * ldc + c;
                if (Rp) {
                    float2 rr = *reinterpret_cast<const float2*>(&Rp[ci]);
                    vx += rr.x; vy += rr.y;
                }
                if (OUTC) {
                    reinterpret_cast<uint2*>(C)[ci >> 1] = split2(vx, vy);
                } else {
                    float2 o; o.x = vx; o.y = vy;
                    *reinterpret_cast<float2*>(&C[ci]) = o;
                }
            }
        }
    }
}

// ---------------- V transpose (cells -> transposed cells) --------------------
__global__ __launch_bounds__(256) void vtrans_kernel(const uint2* __restrict__ qc,
                                                     uint2* __restrict__ vt) {
    __shared__ ushort hiS[32][33];
    __shared__ ushort loS[32][33];
    int bh = blockIdx.z;
    int b = bh >> 4, h = bh & 15;
    int lb = blockIdx.x * 32, db = blockIdx.y * 32;
    int t = threadIdx.x;
    int l = t >> 3, cj = t & 7;
#pragma unroll
    for (int p = 0; p < 2; p++) {
        int j = cj + 8 * p;  // local d-cell 0..15
        long long idx = (long long)(b * LL + lb + l) * (E3 / 2) + 1024 + h * 32 + (db >> 1) + j;
        uint2 cell = qc[idx];
        hiS[l][2 * j]     = (ushort)(cell.x & 0xffffu);
        hiS[l][2 * j + 1] = (ushort)(cell.x >> 16);
        loS[l][2 * j]     = (ushort)(cell.y & 0xffffu);
        loS[l][2 * j + 1] = (ushort)(cell.y >> 16);
    }
    __syncthreads();
    int d = t >> 3;
#pragma unroll
    for (int p = 0; p < 2; p++) {
        int jj = cj + 8 * p;  // local l-pair 0..15
        uint2 cell;
        cell.x = (uint32_t)hiS[2 * jj][d] | ((uint32_t)hiS[2 * jj + 1][d] << 16);
        cell.y = (uint32_t)loS[2 * jj][d] | ((uint32_t)loS[2 * jj + 1][d] << 16);
        long long dst = (long long)bh * (DD * LL / 2) + (long long)(db + d) * (LL / 2) + (lb >> 1) + jj;
        vt[dst] = cell;
    }
}

// ---------------- block reductions -----------------------------------------
__device__ __forceinline__ float blk_reduce_sum(float v, float* sm) {
#pragma unroll
    for (int o = 16; o > 0; o >>= 1) v += __shfl_xor_sync(0xffffffffu, v, o);
    int w = threadIdx.x >> 5;
    if ((threadIdx.x & 31) == 0) sm[w] = v;
    __syncthreads();
    if (threadIdx.x == 0) {
        float s = 0.f;
        int nw = blockDim.x >> 5;
        for (int i = 0; i < nw; i++) s += sm[i];
        sm[0] = s;
    }
    __syncthreads();
    float r = sm[0];
    __syncthreads();
    return r;
}

__device__ __forceinline__ float blk_reduce_max(float v, float* sm) {
#pragma unroll
    for (int o = 16; o > 0; o >>= 1)
        v = fmaxf(v, __shfl_xor_sync(0xffffffffu, v, o));
    int w = threadIdx.x >> 5;
    if ((threadIdx.x & 31) == 0) sm[w] = v;
    __syncthreads();
    if (threadIdx.x == 0) {
        float s = sm[0];
        int nw = blockDim.x >> 5;
        for (int i = 1; i < nw; i++) s = fmaxf(s, sm[i]);
        sm[0] = s;
    }
    __syncthreads();
    float r = sm[0];
    __syncthreads();
    return r;
}

// ---------------- softmax: read S fp32, write W bf16 (hi only) ---------------
__global__ __launch_bounds__(256) void softmax_kernel(const float* __restrict__ S,
                                                      unsigned* __restrict__ Wb) {
    __shared__ float sm[32];
    long long row = blockIdx.x;
    const float* p = S + row * (long long)LL;
    float4 v = reinterpret_cast<const float4*>(p)[threadIdx.x];
    float mx = fmaxf(fmaxf(v.x, v.y), fmaxf(v.z, v.w));
    mx = blk_reduce_max(mx, sm);
    v.x = __expf(v.x - mx);
    v.y = __expf(v.y - mx);
    v.z = __expf(v.z - mx);
    v.w = __expf(v.w - mx);
    float s = v.x + v.y + v.z + v.w;
    s = blk_reduce_sum(s, sm);
    float inv = 1.f / s;
    v.x *= inv; v.y *= inv; v.z *= inv; v.w *= inv;
    uint32_t p0, p1;
    asm("cvt.rn.bf16x2.f32 %0, %1, %2;" : "=r"(p0) : "f"(v.y), "f"(v.x));
    asm("cvt.rn.bf16x2.f32 %0, %1, %2;" : "=r"(p1) : "f"(v.w), "f"(v.z));
    reinterpret_cast<uint2*>(Wb + row * 512)[threadIdx.x] = make_uint2(p0, p1);
}

// ---------------- avg_attn from bf16 W ---------------------------------------
__global__ __launch_bounds__(256) void avg_part_kernel(const unsigned* __restrict__ Wb,
                                                       float* __restrict__ ap) {
    int m2 = blockIdx.x * 256 + threadIdx.x;   // column-pair index
    int lc = blockIdx.y;
    int bh = blockIdx.z;
    const unsigned* p = Wb + (long long)bh * LL * (LL / 2) +
                        (long long)lc * 128 * (LL / 2) + m2;
    float s0 = 0.f, s1 = 0.f;
#pragma unroll 8
    for (int l = 0; l < 128; l++) {
        unsigned u = p[(long long)l * (LL / 2)];
        s0 += __uint_as_float(u << 16);
        s1 += __uint_as_float(u & 0xffff0000u);
    }
    float* dst = ap + ((bh * 8 + lc) * LL) + 2 * m2;
    dst[0] = s0;
    dst[1] = s1;
}

__global__ __launch_bounds__(256) void avg_final_kernel(const float* __restrict__ ap,
                                                        float* __restrict__ out) {
    int m = blockIdx.x * 256 + threadIdx.x;
    int b = blockIdx.y;
    float s = 0.f;
#pragma unroll
    for (int h = 0; h < HH; h++)
#pragma unroll
        for (int lc = 0; lc < 8; lc++)
            s += ap[((b * HH + h) * 8 + lc) * LL + m];
    out[BB * EE + b * LL + m] = s * (1.f / (HH * (float)LL));
}

// ---------------- LayerNorm ---------------------------------------------------
__global__ __launch_bounds__(256) void ln_kernel(const float* __restrict__ h,
                                                 const float* __restrict__ gamma,
                                                 const float* __restrict__ beta,
                                                 float* __restrict__ hn) {
    __shared__ float sm[32];
    long long row = blockIdx.x;
    const float* p = h + row * (long long)EE;
    float4 v = reinterpret_cast<const float4*>(p)[threadIdx.x];
    float s = v.x + v.y + v.z + v.w;
    s = blk_reduce_sum(s, sm);
    float mean = s * (1.f / EE);
    float dx = v.x - mean, dy = v.y - mean, dz = v.z - mean, dw = v.w - mean;
    float sq = dx * dx + dy * dy + dz * dz + dw * dw;
    sq = blk_reduce_sum(sq, sm);
    float r = rsqrtf(sq * (1.f / EE) + EPS);
    float4 gm = reinterpret_cast<const float4*>(gamma)[threadIdx.x];
    float4 bt = reinterpret_cast<const float4*>(beta)[threadIdx.x];
    float4 o;
    o.x = dx * r * gm.x + bt.x;
    o.y = dy * r * gm.y + bt.y;
    o.z = dz * r * gm.z + bt.z;
    o.w = dw * r * gm.w + bt.w;
    reinterpret_cast<float4*>(hn + row * (long long)EE)[threadIdx.x] = o;
}

// ---------------- pooled mean -------------------------------------------------
__global__ __launch_bounds__(256) void pooled_part_kernel(const float* __restrict__ hn,
                                                          float* __restrict__ pp) {
    int e = blockIdx.x * 256 + threadIdx.x;
    int lc = blockIdx.y;
    int b = blockIdx.z;
    const float* p = hn + ((long long)b * LL + lc * 128) * EE + e;
    float s = 0.f;
#pragma unroll 8
    for (int l = 0; l < 128; l++) s += p[(long long)l * EE];
    pp[(b * 8 + lc) * EE + e] = s;
}

__global__ __launch_bounds__(256) void pooled_final_kernel(const float* __restrict__ pp,
                                                           float* __restrict__ out) {
    int e = blockIdx.x * 256 + threadIdx.x;
    int b = blockIdx.y;
    float s = 0.f;
#pragma unroll
    for (int lc = 0; lc < 8; lc++) s += pp[(b * 8 + lc) * EE + e];
    out[b * EE + e] = s * (1.f / (float)LL);
}

// ---------------- launch -----------------------------------------------------
extern "C" void kernel_launch(void* const* d_in, const int* in_sizes, int n_in,
                              void* d_out, int out_size) {
    const float* x     = (const float*)d_in[0];
    const float* w_qkv = (const float*)d_in[1];
    const float* b_qkv = (const float*)d_in[2];
    const float* w_out = (const float*)d_in[3];
    const float* b_out = (const float*)d_in[4];
    const float* gamma = (const float*)d_in[5];
    const float* beta  = (const float*)d_in[6];
    float* out = (float*)d_out;

    uint2 *qkvc, *vtc, *ctxc, *xc, *wqc, *woc;
    unsigned* wb;
    float *S, *res, *hn, *ap, *pp;
    cudaGetSymbolAddress((void**)&qkvc, g_qkvc);
    cudaGetSymbolAddress((void**)&S,    g_S);
    cudaGetSymbolAddress((void**)&wb,   g_wb);
    cudaGetSymbolAddress((void**)&vtc,  g_vtc);
    cudaGetSymbolAddress((void**)&ctxc, g_ctxc);
    cudaGetSymbolAddress((void**)&xc,   g_xc);
    cudaGetSymbolAddress((void**)&wqc,  g_wqc);
    cudaGetSymbolAddress((void**)&woc,  g_woc);
    cudaGetSymbolAddress((void**)&res,  g_res);
    cudaGetSymbolAddress((void**)&hn,   g_hn);
    cudaGetSymbolAddress((void**)&ap,   g_avgpart);
    cudaGetSymbolAddress((void**)&pp,   g_poolpart);

    const int M = BB * LL;  // 8192
    constexpr int KPS = 12;
    const int SM_SPLIT128 = 3 * (128 * KPS * 8 + 128 * KPS * 8);  // 73728
    const int SM_HI64     = 3 * (128 * KPS * 4 + 64 * KPS * 8);   // 36864
    cudaFuncSetAttribute((const void*)cgemm<128, true, true>,
                         cudaFuncAttributeMaxDynamicSharedMemorySize, SM_SPLIT128);
    cudaFuncSetAttribute((const void*)cgemm<128, true, false>,
                         cudaFuncAttributeMaxDynamicSharedMemorySize, SM_SPLIT128);
    cudaFuncSetAttribute((const void*)cgemm<64, false, true>,
                         cudaFuncAttributeMaxDynamicSharedMemorySize, SM_HI64);

    // 0) pre-split inputs to bf16 cells
    split_kernel<<<512, 256>>>((const float2*)x, xc, BB * LL * EE / 2);
    split_kernel<<<512, 256>>>((const float2*)w_qkv, wqc, E3 * EE / 2);
    split_kernel<<<256, 256>>>((const float2*)w_out, woc, EE * EE / 2);

    // 1) QKV projection -> qkv cells (8192 x 3072 x 1024)
    {
        dim3 grid(E3 / 128, M / 128, 1);
        cgemm<128, true, true><<<grid, 256, SM_SPLIT128>>>(
            xc, wqc, (float*)qkvc, b_qkv, nullptr,
            EE, EE / 2, EE / 2, E3,
            0, 0, 0, 0, 0, 0, 1, 1.0f);
    }

    // 1b) Vt cells
    {
        dim3 grid(LL / 32, DD / 32, BB * HH);
        vtrans_kernel<<<grid, 256>>>(qkvc, vtc);
    }

    // 2) scores -> S fp32 (1024x1024x64, 128 batches)
    {
        dim3 grid(LL / 128, LL / 128, BB * HH);
        cgemm<128, true, false><<<grid, 256, SM_SPLIT128>>>(
            qkvc /*Q*/, qkvc + EE / 2 /*K*/, S, nullptr, nullptr,
            DD, E3 / 2, E3 / 2, LL,
            (long long)LL * E3 / 2, DD / 2,
            (long long)LL * E3 / 2, DD / 2,
            (long long)HH * LL * LL, (long long)LL * LL,
            HH, 0.125f);
    }

    // 3) softmax -> W bf16
    softmax_kernel<<<BB * HH * LL, 256>>>(S, wb);

    // 4) avg_attn
    {
        dim3 g1(LL / 512, 8, BB * HH);
        avg_part_kernel<<<g1, 256>>>(wb, ap);
        dim3 g2(LL / 256, BB);
        avg_final_kernel<<<g2, 256>>>(ap, out);
    }

    // 5) ctx = W(bf16 hi) @ Vt^T -> ctx cells (1024 x 64 x 1024, 128 batches)
    {
        dim3 grid(1, LL / 128, BB * HH);
        cgemm<64, false, true><<<grid, 256, SM_HI64>>>(
            wb, vtc, (float*)ctxc, nullptr, nullptr,
            LL, LL / 2, LL / 2, EE,
            (long long)HH * LL * LL / 2, (long long)LL * LL / 2,
            (long long)HH * DD * LL / 2, (long long)DD * LL / 2,
            (long long)LL * EE, (long long)DD,
            HH, 1.0f);
    }

    // 6) out proj + bias + residual -> res fp32
    {
        dim3 grid(EE / 128, M / 128, 1);
        cgemm<128, true, false><<<grid, 256, SM_SPLIT128>>>(
            ctxc, woc, res, b_out, x,
            EE, EE / 2, EE / 2, EE,
            0, 0, 0, 0, 0, 0, 1, 1.0f);
    }

    // 7) layernorm
    ln_kernel<<<M, 256>>>(res, gamma, beta, hn);

    // 8) pooled mean
    {
        dim3 g1(EE / 256, 8, BB);
        pooled_part_kernel<<<g1, 256>>>(hn, pp);
        dim3 g2(EE / 256, BB);
        pooled_final_kernel<<<g2, 256>>>(pp, out);
    }
}

// round 15
// speedup vs baseline: 1.2524x; 1.0930x over previous
#include <cuda_runtime.h>
#include <cuda_bf16.h>
#include <math.h>
#include <stdint.h>

// Problem dims (fixed)
#define BB 8
#define LL 1024
#define EE 1024
#define HH 16
#define DD 64
#define E3 3072
#define EPS 1e-5f

// ---- paired-cell permutation ------------------------------------------------
// Within every 8-cell K16 group, cells are stored in order [0,4,1,5,2,6,3,7]:
//   pos(w)  = ((w&3)<<1) | (w>>2)      (logical cell w -> storage position)
//   cell(p) = ((p&1)<<2) | (p>>1)      (inverse)
// This makes the mma fragment cells (tg, tg+4) 16B-contiguous -> 1 LDS.128.
#define POSW(w)   ((((w) & 3) << 1) | ((w) >> 2))
#define CELLOF(p) ((((p) & 1) << 2) | ((p) >> 1))

// ---------------- scratch (device globals; no allocation allowed) ----------
// "cell" = uint2 {hi_bf16x2, lo_bf16x2} for a pair of consecutive-K fp32 values.
// All cell buffers use the paired-cell permuted order.
__device__ __align__(128) uint2 g_qkvc[BB * LL * E3 / 2];               // 100 MB
__device__ float g_S[(size_t)BB * HH * LL * LL];                         // 512 MB
__device__ __align__(128) unsigned g_wb[(size_t)BB * HH * LL * LL / 2];  // W bf16 hi, 256 MB
__device__ __align__(128) uint2 g_vtc[BB * HH * DD * LL / 2];            // Vt cells, 32 MB
__device__ __align__(128) uint2 g_ctxc[BB * LL * EE / 2];                // ctx cells, 32 MB
__device__ __align__(128) uint2 g_xc[BB * LL * EE / 2];                  // x cells, 32 MB
__device__ __align__(128) uint2 g_wqc[E3 * EE / 2];                      // w_qkv cells, 12 MB
__device__ __align__(128) uint2 g_woc[EE * EE / 2];                      // w_out cells, 4 MB
__device__ float g_res[BB * LL * EE];                                    // 32 MB
__device__ float g_hn[BB * LL * EE];                                     // 32 MB
__device__ float g_avgpart[BB * HH * 8 * LL];
__device__ float g_poolpart[BB * 8 * EE];

// ---------------- helpers ----------------------------------------------------
__device__ __forceinline__ uint2 split2(float x0, float x1) {
    uint32_t hp, lp;
    asm("cvt.rn.bf16x2.f32 %0, %1, %2;" : "=r"(hp) : "f"(x1), "f"(x0));
    float h0 = __uint_as_float(hp << 16);
    float h1 = __uint_as_float(hp & 0xffff0000u);
    float l0 = x0 - h0;
    float l1 = x1 - h1;
    asm("cvt.rn.bf16x2.f32 %0, %1, %2;" : "=r"(lp) : "f"(l1), "f"(l0));
    return make_uint2(hp, lp);
}

__device__ __forceinline__ void mma16(float* d, const uint32_t* a, const uint32_t* b) {
    asm volatile(
        "mma.sync.aligned.m16n8k16.row.col.f32.bf16.bf16.f32 "
        "{%0,%1,%2,%3}, {%4,%5,%6,%7}, {%8,%9}, {%0,%1,%2,%3};"
        : "+f"(d[0]), "+f"(d[1]), "+f"(d[2]), "+f"(d[3])
        : "r"(a[0]), "r"(a[1]), "r"(a[2]), "r"(a[3]), "r"(b[0]), "r"(b[1]));
}

__device__ __forceinline__ void cp16(uint32_t dst, const void* src) {
    asm volatile("cp.async.cg.shared.global [%0], [%1], 16;"
                 :: "r"(dst), "l"(__cvta_generic_to_global(src)) : "memory");
}
__device__ __forceinline__ void cp_commit() {
    asm volatile("cp.async.commit_group;" ::: "memory");
}
template <int N>
__device__ __forceinline__ void cp_wait() {
    asm volatile("cp.async.wait_group %0;" :: "n"(N) : "memory");
}

// ---------------- pre-split kernel: fp32 -> permuted cells -------------------
__global__ __launch_bounds__(256) void split_kernel(const float2* __restrict__ src,
                                                    uint2* __restrict__ dst, int n) {
    int i = blockIdx.x * 256 + threadIdx.x;
    int stride = gridDim.x * 256;
    for (; i < n; i += stride) {
        float2 v = src[i];
        dst[(i & ~7) | POSW(i & 7)] = split2(v.x, v.y);
    }
}

// ---------------- cp.async bf16-cell tensor-core GEMM ------------------------
// C[128*gy, TN*gx] = alpha * A(M,K) * B(N,K)^T (+bias) (+resid)
// A: ASPLIT ? uint2 cells (3-term) : uint hi-cells (2-term). B: uint2 cells.
// All cell buffers permuted (paired-cell). ld*C in cells. OUTC: write permuted
// cells (else fp32). Batched via blockIdx.z = bo*inner + bi.
// 3-stage cp.async ring, one __syncthreads per K16 chunk, 2 CTAs/SM.
template <int TN, bool ASPLIT, bool OUTC>
__global__ __launch_bounds__(256, 2) void cgemm(
    const void* __restrict__ Ap_, const uint2* __restrict__ Bp,
    float* __restrict__ C,
    const float* __restrict__ bias, const float* __restrict__ resid,
    int K, int ldaC, int ldbC, int ldc,
    long long sAo, long long sAi, long long sBo, long long sBi,
    long long sCo, long long sCi, int inner, float alpha)
{
    extern __shared__ __align__(16) char sm[];
    // rows are dense: split rows = 64B (8 uint2 cells), hi rows = 32B
    constexpr int ABYTES = ASPLIT ? 128 * 64 : 128 * 32;
    constexpr int BBYTES = TN * 64;
    constexpr int SLOT = ABYTES + BBYTES;

    const int tid = threadIdx.x;
    const int warp = tid >> 5, lane = tid & 31;
    const int g = lane >> 2, tg = lane & 3;

    int bz = blockIdx.z;
    int bo = bz / inner, bi = bz % inner;
    long long aoff = bo * sAo + bi * sAi;
    Bp += bo * sBo + bi * sBi;
    long long coff = bo * sCo + bi * sCi;
    C += coff;
    const float* Rp = resid ? resid + coff : nullptr;

    const int bm = blockIdx.y * 128;
    const int bn = blockIdx.x * TN;

    constexpr int WN = TN / 4;        // 32 or 16
    constexpr int MT = 4;
    constexpr int NTL = WN / 8;       // 4 or 2
    const int wm = (warp >> 2) * 64;
    const int wn = (warp & 3) * WN;

    float acc[MT][NTL][4];
#pragma unroll
    for (int i = 0; i < MT; i++)
#pragma unroll
        for (int j = 0; j < NTL; j++)
#pragma unroll
            for (int q = 0; q < 4; q++) acc[i][j][q] = 0.f;

    uint32_t sb;
    asm("{ .reg .u64 t; cvta.to.shared.u64 t, %1; cvt.u32.u64 %0, t; }"
        : "=r"(sb) : "l"(sm));

    // ---- precomputed staging pointers (advance by 8 cells per chunk)
    const int r0 = tid >> 2, j4 = tid & 3;        // 64-row groups, 16B chunk
    const int r1 = tid >> 1, j2 = tid & 1;        // 128 rows, 16B chunk (hi-only A)
    const uint2* aS0;
    const uint2* aS1;
    const unsigned* aH;
    if (ASPLIT) {
        const uint2* A2 = (const uint2*)Ap_ + aoff;
        aS0 = A2 + (long long)(bm + r0) * ldaC + 2 * j4;
        aS1 = A2 + (long long)(bm + r0 + 64) * ldaC + 2 * j4;
        aH = nullptr;
    } else {
        const unsigned* A1 = (const unsigned*)Ap_ + aoff;
        aH = A1 + (long long)(bm + r1) * ldaC + 4 * j2;
        aS0 = aS1 = nullptr;
    }
    const uint2* bS0 = Bp + (long long)(bn + r0) * ldbC + 2 * j4;
    const uint2* bS1 = (TN == 128) ? Bp + (long long)(bn + r0 + 64) * ldbC + 2 * j4
                                   : nullptr;
    const uint32_t aD0 = ASPLIT ? (uint32_t)(r0 * 64 + 16 * j4)
                                : (uint32_t)(r1 * 32 + 16 * j2);
    const uint32_t aD1 = ASPLIT ? (uint32_t)((r0 + 64) * 64 + 16 * j4) : 0;
    const uint32_t bD0 = (uint32_t)(ABYTES + r0 * 64 + 16 * j4);
    const uint32_t bD1 = (uint32_t)(ABYTES + (r0 + 64) * 64 + 16 * j4);

    const int nc = K / 16;

    auto stage = [&](int c, int slot) {
        uint32_t base = sb + slot * SLOT;
        if (ASPLIT) {
            cp16(base + aD0, aS0 + c * 8);
            cp16(base + aD1, aS1 + c * 8);
        } else {
            cp16(base + aD0, aH + c * 8);
        }
        cp16(base + bD0, bS0 + c * 8);
        if (TN == 128) cp16(base + bD1, bS1 + c * 8);
    };

    stage(0, 0); cp_commit();
    stage(1, 1); cp_commit();

    int slot = 0;
    for (int c = 0; c < nc; c++) {
        if (c + 1 < nc) cp_wait<1>();
        else            cp_wait<0>();
        __syncthreads();
        {
            int ns = slot + 2; if (ns >= 3) ns -= 3;
            if (c + 2 < nc) { stage(c + 2, ns); cp_commit(); }
        }

        const char* slotbase = sm + slot * SLOT;
        const char* bsc = slotbase + ABYTES;

        // B fragments: one LDS.128 per nt (cells tg & tg+4 are adjacent)
        uint32_t bh[NTL][2], bl[NTL][2];
#pragma unroll
        for (int nt = 0; nt < NTL; nt++) {
            uint4 q = *reinterpret_cast<const uint4*>(
                bsc + (wn + nt * 8 + g) * 64 + tg * 16);
            bh[nt][0] = q.x; bh[nt][1] = q.z;
            bl[nt][0] = q.y; bl[nt][1] = q.w;
        }

        if (ASPLIT) {
#pragma unroll
            for (int mt = 0; mt < MT; mt++) {
                int rr = wm + mt * 16 + g;
                uint4 qa = *reinterpret_cast<const uint4*>(slotbase + rr * 64 + tg * 16);
                uint4 qb = *reinterpret_cast<const uint4*>(slotbase + (rr + 8) * 64 + tg * 16);
                uint32_t ah[4] = {qa.x, qb.x, qa.z, qb.z};
                uint32_t al[4] = {qa.y, qb.y, qa.w, qb.w};
#pragma unroll
                for (int nt = 0; nt < NTL; nt++) {
                    mma16(acc[mt][nt], ah, bh[nt]);
                    mma16(acc[mt][nt], ah, bl[nt]);
                    mma16(acc[mt][nt], al, bh[nt]);
                }
            }
        } else {
#pragma unroll
            for (int mt = 0; mt < MT; mt++) {
                int rr = wm + mt * 16 + g;
                uint2 ua = *reinterpret_cast<const uint2*>(slotbase + rr * 32 + tg * 8);
                uint2 ub = *reinterpret_cast<const uint2*>(slotbase + (rr + 8) * 32 + tg * 8);
                uint32_t ah[4] = {ua.x, ub.x, ua.y, ub.y};
#pragma unroll
                for (int nt = 0; nt < NTL; nt++) {
                    mma16(acc[mt][nt], ah, bh[nt]);
                    mma16(acc[mt][nt], ah, bl[nt]);
                }
            }
        }
        slot = (slot == 2) ? 0 : slot + 1;
    }

    // ---- epilogue
#pragma unroll
    for (int mt = 0; mt < MT; mt++) {
#pragma unroll
        for (int nt = 0; nt < NTL; nt++) {
            int c = bn + wn + nt * 8 + 2 * tg;
#pragma unroll
            for (int hrow = 0; hrow < 2; hrow++) {
                int gr = bm + wm + mt * 16 + g + hrow * 8;
                float vx = acc[mt][nt][2 * hrow] * alpha;
                float vy = acc[mt][nt][2 * hrow + 1] * alpha;
                if (bias) { vx += bias[c]; vy += bias[c + 1]; }
                long long ci = (long long)gr * ldc + c;
                if (Rp) {
                    float2 rr = *reinterpret_cast<const float2*>(&Rp[ci]);
                    vx += rr.x; vy += rr.y;
                }
                if (OUTC) {
                    long long k = ci >> 1;
                    long long kp = (k & ~7LL) | (long long)POSW((int)(k & 7));
                    reinterpret_cast<uint2*>(C)[kp] = split2(vx, vy);
                } else {
                    float2 o; o.x = vx; o.y = vy;
                    *reinterpret_cast<float2*>(&C[ci]) = o;
                }
            }
        }
    }
}

// ---------------- V transpose (permuted cells -> permuted transposed cells) --
__global__ __launch_bounds__(256) void vtrans_kernel(const uint2* __restrict__ qc,
                                                     uint2* __restrict__ vt) {
    __shared__ ushort hiS[32][33];
    __shared__ ushort loS[32][33];
    int bh = blockIdx.z;
    int b = bh >> 4, h = bh & 15;
    int lb = blockIdx.x * 32, db = blockIdx.y * 32;
    int t = threadIdx.x;
    int l = t >> 3, cj = t & 7;
#pragma unroll
    for (int p = 0; p < 2; p++) {
        int j = cj + 8 * p;  // local d-cell 0..15 (logical)
        long long base = (long long)(b * LL + lb + l) * (E3 / 2) + 1024 + h * 32 + (db >> 1);
        long long idx = base + (j & ~7) + POSW(j & 7);
        uint2 cell = qc[idx];
        hiS[l][2 * j]     = (ushort)(cell.x & 0xffffu);
        hiS[l][2 * j + 1] = (ushort)(cell.x >> 16);
        loS[l][2 * j]     = (ushort)(cell.y & 0xffffu);
        loS[l][2 * j + 1] = (ushort)(cell.y >> 16);
    }
    __syncthreads();
    int d = t >> 3;
#pragma unroll
    for (int p = 0; p < 2; p++) {
        int jj = cj + 8 * p;  // local l-pair 0..15 (logical)
        uint2 cell;
        cell.x = (uint32_t)hiS[2 * jj][d] | ((uint32_t)hiS[2 * jj + 1][d] << 16);
        cell.y = (uint32_t)loS[2 * jj][d] | ((uint32_t)loS[2 * jj + 1][d] << 16);
        long long base = (long long)bh * (DD * LL / 2) + (long long)(db + d) * (LL / 2) + (lb >> 1);
        long long dst = base + (jj & ~7) + POSW(jj & 7);
        vt[dst] = cell;
    }
}

// ---------------- block reductions -----------------------------------------
__device__ __forceinline__ float blk_reduce_sum(float v, float* sm) {
#pragma unroll
    for (int o = 16; o > 0; o >>= 1) v += __shfl_xor_sync(0xffffffffu, v, o);
    int w = threadIdx.x >> 5;
    if ((threadIdx.x & 31) == 0) sm[w] = v;
    __syncthreads();
    if (threadIdx.x == 0) {
        float s = 0.f;
        int nw = blockDim.x >> 5;
        for (int i = 0; i < nw; i++) s += sm[i];
        sm[0] = s;
    }
    __syncthreads();
    float r = sm[0];
    __syncthreads();
    return r;
}

__device__ __forceinline__ float blk_reduce_max(float v, float* sm) {
#pragma unroll
    for (int o = 16; o > 0; o >>= 1)
        v = fmaxf(v, __shfl_xor_sync(0xffffffffu, v, o));
    int w = threadIdx.x >> 5;
    if ((threadIdx.x & 31) == 0) sm[w] = v;
    __syncthreads();
    if (threadIdx.x == 0) {
        float s = sm[0];
        int nw = blockDim.x >> 5;
        for (int i = 1; i < nw; i++) s = fmaxf(s, sm[i]);
        sm[0] = s;
    }
    __syncthreads();
    float r = sm[0];
    __syncthreads();
    return r;
}

// ---------------- softmax: read S fp32, write W bf16 hi (permuted cells) -----
// Thread t handles the 4 values that land in its output uint2 (positions 2t,
// 2t+1 = logical cells (t&3) and (t&3)+4 of group t>>2):
//   columns 16*(t>>2) + 2*(t&3) + {0,1}  and  +8 + {0,1}.
__global__ __launch_bounds__(256) void softmax_kernel(const float* __restrict__ S,
                                                      unsigned* __restrict__ Wb) {
    __shared__ float sm[32];
    long long row = blockIdx.x;
    int t = threadIdx.x;
    int grp = t >> 2, u = t & 3;
    const float* p = S + row * (long long)LL + grp * 16 + 2 * u;
    float2 va = *reinterpret_cast<const float2*>(p);
    float2 vb = *reinterpret_cast<const float2*>(p + 8);
    float mx = fmaxf(fmaxf(va.x, va.y), fmaxf(vb.x, vb.y));
    mx = blk_reduce_max(mx, sm);
    va.x = __expf(va.x - mx);
    va.y = __expf(va.y - mx);
    vb.x = __expf(vb.x - mx);
    vb.y = __expf(vb.y - mx);
    float s = va.x + va.y + vb.x + vb.y;
    s = blk_reduce_sum(s, sm);
    float inv = 1.f / s;
    va.x *= inv; va.y *= inv; vb.x *= inv; vb.y *= inv;
    uint32_t p0, p1;
    asm("cvt.rn.bf16x2.f32 %0, %1, %2;" : "=r"(p0) : "f"(va.y), "f"(va.x));
    asm("cvt.rn.bf16x2.f32 %0, %1, %2;" : "=r"(p1) : "f"(vb.y), "f"(vb.x));
    reinterpret_cast<uint2*>(Wb + row * 512)[t] = make_uint2(p0, p1);
}

// ---------------- avg_attn from permuted bf16 W ------------------------------
__global__ __launch_bounds__(256) void avg_part_kernel(const unsigned* __restrict__ Wb,
                                                       float* __restrict__ ap) {
    int m2 = blockIdx.x * 256 + threadIdx.x;   // storage-position index
    int lc = blockIdx.y;
    int bh = blockIdx.z;
    const unsigned* p = Wb + (long long)bh * LL * (LL / 2) +
                        (long long)lc * 128 * (LL / 2) + m2;
    float s0 = 0.f, s1 = 0.f;
#pragma unroll 8
    for (int l = 0; l < 128; l++) {
        unsigned u = p[(long long)l * (LL / 2)];
        s0 += __uint_as_float(u << 16);
        s1 += __uint_as_float(u & 0xffff0000u);
    }
    int cbase = 16 * (m2 >> 3) + 2 * CELLOF(m2 & 7);   // logical column
    float* dst = ap + ((bh * 8 + lc) * LL) + cbase;
    dst[0] = s0;
    dst[1] = s1;
}

__global__ __launch_bounds__(256) void avg_final_kernel(const float* __restrict__ ap,
                                                        float* __restrict__ out) {
    int m = blockIdx.x * 256 + threadIdx.x;
    int b = blockIdx.y;
    float s = 0.f;
#pragma unroll
    for (int h = 0; h < HH; h++)
#pragma unroll
        for (int lc = 0; lc < 8; lc++)
            s += ap[((b * HH + h) * 8 + lc) * LL + m];
    out[BB * EE + b * LL + m] = s * (1.f / (HH * (float)LL));
}

// ---------------- LayerNorm ---------------------------------------------------
__global__ __launch_bounds__(256) void ln_kernel(const float* __restrict__ h,
                                                 const float* __restrict__ gamma,
                                                 const float* __restrict__ beta,
                                                 float* __restrict__ hn) {
    __shared__ float sm[32];
    long long row = blockIdx.x;
    const float* p = h + row * (long long)EE;
    float4 v = reinterpret_cast<const float4*>(p)[threadIdx.x];
    float s = v.x + v.y + v.z + v.w;
    s = blk_reduce_sum(s, sm);
    float mean = s * (1.f / EE);
    float dx = v.x - mean, dy = v.y - mean, dz = v.z - mean, dw = v.w - mean;
    float sq = dx * dx + dy * dy + dz * dz + dw * dw;
    sq = blk_reduce_sum(sq, sm);
    float r = rsqrtf(sq * (1.f / EE) + EPS);
    float4 gm = reinterpret_cast<const float4*>(gamma)[threadIdx.x];
    float4 bt = reinterpret_cast<const float4*>(beta)[threadIdx.x];
    float4 o;
    o.x = dx * r * gm.x + bt.x;
    o.y = dy * r * gm.y + bt.y;
    o.z = dz * r * gm.z + bt.z;
    o.w = dw * r * gm.w + bt.w;
    reinterpret_cast<float4*>(hn + row * (long long)EE)[threadIdx.x] = o;
}

// ---------------- pooled mean -------------------------------------------------
__global__ __launch_bounds__(256) void pooled_part_kernel(const float* __restrict__ hn,
                                                          float* __restrict__ pp) {
    int e = blockIdx.x * 256 + threadIdx.x;
    int lc = blockIdx.y;
    int b = blockIdx.z;
    const float* p = hn + ((long long)b * LL + lc * 128) * EE + e;
    float s = 0.f;
#pragma unroll 8
    for (int l = 0; l < 128; l++) s += p[(long long)l * EE];
    pp[(b * 8 + lc) * EE + e] = s;
}

__global__ __launch_bounds__(256) void pooled_final_kernel(const float* __restrict__ pp,
                                                           float* __restrict__ out) {
    int e = blockIdx.x * 256 + threadIdx.x;
    int b = blockIdx.y;
    float s = 0.f;
#pragma unroll
    for (int lc = 0; lc < 8; lc++) s += pp[(b * 8 + lc) * EE + e];
    out[b * EE + e] = s * (1.f / (float)LL);
}

// ---------------- launch -----------------------------------------------------
extern "C" void kernel_launch(void* const* d_in, const int* in_sizes, int n_in,
                              void* d_out, int out_size) {
    const float* x     = (const float*)d_in[0];
    const float* w_qkv = (const float*)d_in[1];
    const float* b_qkv = (const float*)d_in[2];
    const float* w_out = (const float*)d_in[3];
    const float* b_out = (const float*)d_in[4];
    const float* gamma = (const float*)d_in[5];
    const float* beta  = (const float*)d_in[6];
    float* out = (float*)d_out;

    uint2 *qkvc, *vtc, *ctxc, *xc, *wqc, *woc;
    unsigned* wb;
    float *S, *res, *hn, *ap, *pp;
    cudaGetSymbolAddress((void**)&qkvc, g_qkvc);
    cudaGetSymbolAddress((void**)&S,    g_S);
    cudaGetSymbolAddress((void**)&wb,   g_wb);
    cudaGetSymbolAddress((void**)&vtc,  g_vtc);
    cudaGetSymbolAddress((void**)&ctxc, g_ctxc);
    cudaGetSymbolAddress((void**)&xc,   g_xc);
    cudaGetSymbolAddress((void**)&wqc,  g_wqc);
    cudaGetSymbolAddress((void**)&woc,  g_woc);
    cudaGetSymbolAddress((void**)&res,  g_res);
    cudaGetSymbolAddress((void**)&hn,   g_hn);
    cudaGetSymbolAddress((void**)&ap,   g_avgpart);
    cudaGetSymbolAddress((void**)&pp,   g_poolpart);

    const int M = BB * LL;  // 8192
    const int SM_SPLIT128 = 3 * (128 * 64 + 128 * 64);  // 49152
    const int SM_HI64     = 3 * (128 * 32 + 64 * 64);   // 24576
    cudaFuncSetAttribute((const void*)cgemm<128, true, true>,
                         cudaFuncAttributeMaxDynamicSharedMemorySize, SM_SPLIT128);
    cudaFuncSetAttribute((const void*)cgemm<128, true, false>,
                         cudaFuncAttributeMaxDynamicSharedMemorySize, SM_SPLIT128);
    cudaFuncSetAttribute((const void*)cgemm<64, false, true>,
                         cudaFuncAttributeMaxDynamicSharedMemorySize, SM_HI64);

    // 0) pre-split inputs to permuted bf16 cells
    split_kernel<<<512, 256>>>((const float2*)x, xc, BB * LL * EE / 2);
    split_kernel<<<512, 256>>>((const float2*)w_qkv, wqc, E3 * EE / 2);
    split_kernel<<<256, 256>>>((const float2*)w_out, woc, EE * EE / 2);

    // 1) QKV projection -> qkv cells (8192 x 3072 x 1024)
    {
        dim3 grid(E3 / 128, M / 128, 1);
        cgemm<128, true, true><<<grid, 256, SM_SPLIT128>>>(
            xc, wqc, (float*)qkvc, b_qkv, nullptr,
            EE, EE / 2, EE / 2, E3,
            0, 0, 0, 0, 0, 0, 1, 1.0f);
    }

    // 1b) Vt cells
    {
        dim3 grid(LL / 32, DD / 32, BB * HH);
        vtrans_kernel<<<grid, 256>>>(qkvc, vtc);
    }

    // 2) scores -> S fp32 (1024x1024x64, 128 batches)
    {
        dim3 grid(LL / 128, LL / 128, BB * HH);
        cgemm<128, true, false><<<grid, 256, SM_SPLIT128>>>(
            qkvc /*Q*/, qkvc + EE / 2 /*K*/, S, nullptr, nullptr,
            DD, E3 / 2, E3 / 2, LL,
            (long long)LL * E3 / 2, DD / 2,
            (long long)LL * E3 / 2, DD / 2,
            (long long)HH * LL * LL, (long long)LL * LL,
            HH, 0.125f);
    }

    // 3) softmax -> W bf16 (permuted)
    softmax_kernel<<<BB * HH * LL, 256>>>(S, wb);

    // 4) avg_attn
    {
        dim3 g1(LL / 512, 8, BB * HH);
        avg_part_kernel<<<g1, 256>>>(wb, ap);
        dim3 g2(LL / 256, BB);
        avg_final_kernel<<<g2, 256>>>(ap, out);
    }

    // 5) ctx = W(bf16 hi) @ Vt^T -> ctx cells (1024 x 64 x 1024, 128 batches)
    {
        dim3 grid(1, LL / 128, BB * HH);
        cgemm<64, false, true><<<grid, 256, SM_HI64>>>(
            wb, vtc, (float*)ctxc, nullptr, nullptr,
            LL, LL / 2, LL / 2, EE,
            (long long)HH * LL * LL / 2, (long long)LL * LL / 2,
            (long long)HH * DD * LL / 2, (long long)DD * LL / 2,
            (long long)LL * EE, (long long)DD,
            HH, 1.0f);
    }

    // 6) out proj + bias + residual -> res fp32
    {
        dim3 grid(EE / 128, M / 128, 1);
        cgemm<128, true, false><<<grid, 256, SM_SPLIT128>>>(
            ctxc, woc, res, b_out, x,
            EE, EE / 2, EE / 2, EE,
            0, 0, 0, 0, 0, 0, 1, 1.0f);
    }

    // 7) layernorm
    ln_kernel<<<M, 256>>>(res, gamma, beta, hn);

    // 8) pooled mean
    {
        dim3 g1(EE / 256, 8, BB);
        pooled_part_kernel<<<g1, 256>>>(hn, pp);
        dim3 g2(EE / 256, BB);
        pooled_final_kernel<<<g2, 256>>>(pp, out);
    }
}